// round 5
// baseline (speedup 1.0000x reference)
#include <cuda_runtime.h>
#include <math.h>

#define SEQ   2048
#define DIM   4096
#define NH    32
#define NKVH  8
#define HD    128
#define KVDIM (NKVH*HD)   /* 1024 */

typedef unsigned long long ull;

// ---------------- scratch (device globals: no allocation allowed) -----------
__device__ float g_Q[SEQ*DIM];        // 32 MB
__device__ float g_K[SEQ*KVDIM];      // 8 MB
__device__ float g_V[SEQ*KVDIM];      // 8 MB
__device__ float g_attn[SEQ*DIM];     // 32 MB
__device__ float g_cos[SEQ*(HD/2)];
__device__ float g_sin[SEQ*(HD/2)];

// ---------------- packed f32x2 helpers --------------------------------------
#define PK2(d, lo, hi) \
    asm("mov.b64 %0, {%1, %2};" : "=l"(d) : "r"(__float_as_uint(lo)), "r"(__float_as_uint(hi)))
#define UPK2(lo, hi, d) do { unsigned int _u0, _u1; \
    asm("mov.b64 {%0, %1}, %2;" : "=r"(_u0), "=r"(_u1) : "l"(d)); \
    (lo) = __uint_as_float(_u0); (hi) = __uint_as_float(_u1); } while (0)
#define FMA2(d, a, b) \
    asm("fma.rn.f32x2 %0, %1, %2, %0;" : "+l"(d) : "l"(a), "l"(b))
#define MUL2(d, a, b) \
    asm("mul.rn.f32x2 %0, %1, %2;" : "=l"(d) : "l"(a), "l"(b))

// ---------------- GEMM: C[M,N] = A[M,K] * B[N,K]^T (both row-major) ---------
// 128x128 tile, BK=8, 256 threads, 8x8 outputs/thread, f32x2 FMAs.
__global__ __launch_bounds__(256) void gemm_nt_f32(
    const float* __restrict__ A, const float* __restrict__ B,
    float* __restrict__ C, int M, int N, int K)
{
    __shared__ float As[8][128];
    __shared__ float Bs[8][128];

    const int tid = threadIdx.x;
    const int tx = tid & 15, ty = tid >> 4;
    const int m0 = blockIdx.y * 128, n0 = blockIdx.x * 128;
    const int lr = tid >> 1;          // 0..127
    const int lc = (tid & 1) * 4;     // 0 or 4

    const float* Ap = A + (size_t)(m0 + lr) * K + lc;
    const float* Bp = B + (size_t)(n0 + lr) * K + lc;

    ull acc[8][4];
#pragma unroll
    for (int i = 0; i < 8; i++)
#pragma unroll
        for (int j = 0; j < 4; j++) acc[i][j] = 0ULL;

    float4 av = *(const float4*)Ap;
    float4 bv = *(const float4*)Bp;

    for (int k0 = 0; k0 < K; k0 += 8) {
        __syncthreads();
        As[lc+0][lr] = av.x; As[lc+1][lr] = av.y; As[lc+2][lr] = av.z; As[lc+3][lr] = av.w;
        Bs[lc+0][lr] = bv.x; Bs[lc+1][lr] = bv.y; Bs[lc+2][lr] = bv.z; Bs[lc+3][lr] = bv.w;
        __syncthreads();

        if (k0 + 8 < K) {           // prefetch next tile
            av = *(const float4*)(Ap + k0 + 8);
            bv = *(const float4*)(Bp + k0 + 8);
        }

#pragma unroll
        for (int kk = 0; kk < 8; kk++) {
            float4 a0 = *(const float4*)&As[kk][ty*8];
            float4 a1 = *(const float4*)&As[kk][ty*8+4];
            float4 b0 = *(const float4*)&Bs[kk][tx*8];
            float4 b1 = *(const float4*)&Bs[kk][tx*8+4];
            ull bb[4];
            PK2(bb[0], b0.x, b0.y); PK2(bb[1], b0.z, b0.w);
            PK2(bb[2], b1.x, b1.y); PK2(bb[3], b1.z, b1.w);
            float aa[8] = {a0.x,a0.y,a0.z,a0.w,a1.x,a1.y,a1.z,a1.w};
#pragma unroll
            for (int i = 0; i < 8; i++) {
                ull ad; PK2(ad, aa[i], aa[i]);
#pragma unroll
                for (int j = 0; j < 4; j++) FMA2(acc[i][j], ad, bb[j]);
            }
        }
    }

#pragma unroll
    for (int i = 0; i < 8; i++) {
        float4 c0, c1;
        UPK2(c0.x, c0.y, acc[i][0]); UPK2(c0.z, c0.w, acc[i][1]);
        UPK2(c1.x, c1.y, acc[i][2]); UPK2(c1.z, c1.w, acc[i][3]);
        float* Cp = C + (size_t)(m0 + ty*8 + i) * N + n0 + tx*8;
        *(float4*)Cp = c0;
        *(float4*)(Cp + 4) = c1;
    }
}

// ---------------- RoPE table + apply ----------------------------------------
__global__ void rope_tab_kernel(float* __restrict__ cosT, float* __restrict__ sinT)
{
    int idx = blockIdx.x * blockDim.x + threadIdx.x;
    if (idx >= SEQ * (HD/2)) return;
    int s = idx / (HD/2);
    int i = idx % (HD/2);
    double freq = pow(500000.0, -(double)(2*i) / (double)HD);
    float ff = (float)freq;
    float ang = (float)s * ff;          // match jax fp32 angle
    cosT[idx] = (float)cos((double)ang);
    sinT[idx] = (float)sin((double)ang);
}

__global__ void rope_apply_kernel(float* __restrict__ X,
                                  const float* __restrict__ cosT,
                                  const float* __restrict__ sinT, int nheads)
{
    int idx = blockIdx.x * blockDim.x + threadIdx.x;
    int total = SEQ * nheads * (HD/2);
    if (idx >= total) return;
    int i = idx % (HD/2);
    int h = (idx / (HD/2)) % nheads;
    int s = idx / ((HD/2) * nheads);
    float c  = cosT[s*(HD/2) + i];
    float sn = sinT[s*(HD/2) + i];
    float* p = X + (size_t)s * (nheads*HD) + h*HD + 2*i;
    float e = p[0], o = p[1];
    p[0] = e*c - o*sn;
    p[1] = e*sn + o*c;
}

// ---------------- Flash attention (fp32, online softmax, causal, GQA) -------
// Block: 64 q-rows of one head. 256 threads (16x16). SMEM: QsT/KsT [128][64],
// Vs [64][128], Ps [64][65].
#define ATTN_SMEM ((128*64 + 128*64 + 64*128 + 64*65) * 4)

__global__ __launch_bounds__(256) void attn_kernel(
    const float* __restrict__ Q, const float* __restrict__ K,
    const float* __restrict__ V, float* __restrict__ O)
{
    extern __shared__ float sm[];
    float* QsT = sm;                  // [128][64] transposed
    float* KsT = QsT + 128*64;        // [128][64] transposed
    float* Vs  = KsT + 128*64;        // [64][128]
    float* Ps  = Vs  + 64*128;        // [64][65]

    const int tid = threadIdx.x;
    const int tx = tid & 15, ty = tid >> 4;
    const int qb = blockIdx.x, h = blockIdx.y;
    const int kvh = h >> 2;
    const int q0 = qb * 64;
    const float scale = 0.08838834764831845f;   // 1/sqrt(128)

    // Load Q tile transposed
#pragma unroll
    for (int it = 0; it < 8; it++) {
        int lin = it * 1024 + tid * 4;
        int r = lin >> 7, c = lin & 127;
        float4 v = *(const float4*)&Q[(size_t)(q0 + r)*DIM + h*HD + c];
        QsT[(c+0)*64 + r] = v.x; QsT[(c+1)*64 + r] = v.y;
        QsT[(c+2)*64 + r] = v.z; QsT[(c+3)*64 + r] = v.w;
    }

    float m[4], l[4];
    ull Oa[4][4];
#pragma unroll
    for (int i = 0; i < 4; i++) {
        m[i] = -INFINITY; l[i] = 0.0f;
#pragma unroll
        for (int j = 0; j < 4; j++) Oa[i][j] = 0ULL;
    }

    for (int kb = 0; kb <= qb; kb++) {
        __syncthreads();
        const int k0 = kb * 64;
#pragma unroll
        for (int it = 0; it < 8; it++) {
            int lin = it * 1024 + tid * 4;
            int r = lin >> 7, c = lin & 127;
            float4 kv4 = *(const float4*)&K[(size_t)(k0 + r)*KVDIM + kvh*HD + c];
            KsT[(c+0)*64 + r] = kv4.x; KsT[(c+1)*64 + r] = kv4.y;
            KsT[(c+2)*64 + r] = kv4.z; KsT[(c+3)*64 + r] = kv4.w;
            float4 vv4 = *(const float4*)&V[(size_t)(k0 + r)*KVDIM + kvh*HD + c];
            *(float4*)&Vs[r*128 + c] = vv4;
        }
        __syncthreads();

        // S = Q K^T (4q x 4k fragment per thread)
        ull sa[4][2];
#pragma unroll
        for (int i = 0; i < 4; i++) { sa[i][0] = 0ULL; sa[i][1] = 0ULL; }
#pragma unroll 4
        for (int d = 0; d < 128; d++) {
            float4 a = *(const float4*)&QsT[d*64 + ty*4];
            float4 b = *(const float4*)&KsT[d*64 + tx*4];
            ull b01, b23; PK2(b01, b.x, b.y); PK2(b23, b.z, b.w);
            float aa[4] = {a.x, a.y, a.z, a.w};
#pragma unroll
            for (int i = 0; i < 4; i++) {
                ull ad; PK2(ad, aa[i], aa[i]);
                FMA2(sa[i][0], ad, b01);
                FMA2(sa[i][1], ad, b23);
            }
        }
        float s[4][4];
#pragma unroll
        for (int i = 0; i < 4; i++) {
            UPK2(s[i][0], s[i][1], sa[i][0]);
            UPK2(s[i][2], s[i][3], sa[i][1]);
        }

        const bool diag = (kb == qb);
#pragma unroll
        for (int i = 0; i < 4; i++)
#pragma unroll
            for (int j = 0; j < 4; j++) {
                s[i][j] *= scale;
                if (diag && (tx*4 + j) > (ty*4 + i)) s[i][j] = -INFINITY;
            }

        // online softmax update
#pragma unroll
        for (int i = 0; i < 4; i++) {
            float v = fmaxf(fmaxf(s[i][0], s[i][1]), fmaxf(s[i][2], s[i][3]));
#pragma unroll
            for (int off = 8; off >= 1; off >>= 1)
                v = fmaxf(v, __shfl_xor_sync(0xffffffffu, v, off));
            float mn = fmaxf(m[i], v);

            float p0 = expf(s[i][0] - mn), p1 = expf(s[i][1] - mn);
            float p2 = expf(s[i][2] - mn), p3 = expf(s[i][3] - mn);
            s[i][0] = p0; s[i][1] = p1; s[i][2] = p2; s[i][3] = p3;
            float ls = p0 + p1 + p2 + p3;
#pragma unroll
            for (int off = 8; off >= 1; off >>= 1)
                ls += __shfl_xor_sync(0xffffffffu, ls, off);

            float alpha = expf(m[i] - mn);
            l[i] = l[i] * alpha + ls;
            m[i] = mn;
            ull am; PK2(am, alpha, alpha);
#pragma unroll
            for (int j = 0; j < 4; j++) { ull t; MUL2(t, Oa[i][j], am); Oa[i][j] = t; }
        }

        // stage P
#pragma unroll
        for (int i = 0; i < 4; i++)
#pragma unroll
            for (int j = 0; j < 4; j++)
                Ps[(ty*4 + i)*65 + tx*4 + j] = s[i][j];
        __syncthreads();

        // O += P V   (4q x 8d per thread, packed as 4 f32x2)
#pragma unroll 2
        for (int kk = 0; kk < 64; kk++) {
            float4 v0 = *(const float4*)&Vs[kk*128 + tx*8];
            float4 v1 = *(const float4*)&Vs[kk*128 + tx*8 + 4];
            ull vv[4];
            PK2(vv[0], v0.x, v0.y); PK2(vv[1], v0.z, v0.w);
            PK2(vv[2], v1.x, v1.y); PK2(vv[3], v1.z, v1.w);
#pragma unroll
            for (int i = 0; i < 4; i++) {
                float p = Ps[(ty*4 + i)*65 + kk];
                ull pd; PK2(pd, p, p);
#pragma unroll
                for (int j = 0; j < 4; j++) FMA2(Oa[i][j], pd, vv[j]);
            }
        }
    }

    // epilogue: divide by row sums, write out
#pragma unroll
    for (int i = 0; i < 4; i++) {
        float inv = 1.0f / l[i];
        float4 o0, o1;
        UPK2(o0.x, o0.y, Oa[i][0]); UPK2(o0.z, o0.w, Oa[i][1]);
        UPK2(o1.x, o1.y, Oa[i][2]); UPK2(o1.z, o1.w, Oa[i][3]);
        o0.x *= inv; o0.y *= inv; o0.z *= inv; o0.w *= inv;
        o1.x *= inv; o1.y *= inv; o1.z *= inv; o1.w *= inv;
        float* Op = O + (size_t)(q0 + ty*4 + i)*DIM + h*HD + tx*8;
        *(float4*)Op = o0;
        *(float4*)(Op + 4) = o1;
    }
}

// ---------------- launch -----------------------------------------------------
extern "C" void kernel_launch(void* const* d_in, const int* in_sizes, int n_in,
                              void* d_out, int out_size)
{
    const float* x  = (const float*)d_in[0];
    const float* wq = (const float*)d_in[1];
    const float* wk = (const float*)d_in[2];
    const float* wv = (const float*)d_in[3];
    const float* wo = (const float*)d_in[4];
    float* out = (float*)d_out;

    float *Qp, *Kp, *Vp, *Ap, *cp, *sp;
    cudaGetSymbolAddress((void**)&Qp, g_Q);
    cudaGetSymbolAddress((void**)&Kp, g_K);
    cudaGetSymbolAddress((void**)&Vp, g_V);
    cudaGetSymbolAddress((void**)&Ap, g_attn);
    cudaGetSymbolAddress((void**)&cp, g_cos);
    cudaGetSymbolAddress((void**)&sp, g_sin);

    cudaFuncSetAttribute(attn_kernel, cudaFuncAttributeMaxDynamicSharedMemorySize,
                         ATTN_SMEM);

    rope_tab_kernel<<<(SEQ*(HD/2) + 255)/256, 256>>>(cp, sp);
    gemm_nt_f32<<<dim3(DIM/128,   SEQ/128), 256>>>(x, wq, Qp, SEQ, DIM,   DIM);
    gemm_nt_f32<<<dim3(KVDIM/128, SEQ/128), 256>>>(x, wk, Kp, SEQ, KVDIM, DIM);
    gemm_nt_f32<<<dim3(KVDIM/128, SEQ/128), 256>>>(x, wv, Vp, SEQ, KVDIM, DIM);
    rope_apply_kernel<<<(SEQ*NH*(HD/2))/256,   256>>>(Qp, cp, sp, NH);
    rope_apply_kernel<<<(SEQ*NKVH*(HD/2))/256, 256>>>(Kp, cp, sp, NKVH);
    attn_kernel<<<dim3(SEQ/64, NH), 256, ATTN_SMEM>>>(Qp, Kp, Vp, Ap);
    gemm_nt_f32<<<dim3(DIM/128, SEQ/128), 256>>>(Ap, wo, out, SEQ, DIM, DIM);
}

// round 11
// speedup vs baseline: 1.7742x; 1.7742x over previous
#include <cuda_runtime.h>
#include <cuda_bf16.h>
#include <math.h>

#define SEQ   2048
#define DIM   4096
#define NH    32
#define NKVH  8
#define HD    128
#define KVDIM (NKVH*HD)   /* 1024 */

typedef unsigned long long ull;
typedef unsigned int uint;

// ---------------- scratch (device globals: no allocation allowed) -----------
__device__ __align__(256) float g_Q[SEQ*DIM];
__device__ __align__(256) float g_K[SEQ*KVDIM];
__device__ __align__(256) float g_V[SEQ*KVDIM];
__device__ __align__(256) float g_attn[SEQ*DIM];
__device__ __align__(256) float g_cos[SEQ*(HD/2)];
__device__ __align__(256) float g_sin[SEQ*(HD/2)];
// split-bf16 operands
__device__ __align__(256) __nv_bfloat16 g_xh[SEQ*DIM],   g_xl[SEQ*DIM];
__device__ __align__(256) __nv_bfloat16 g_ah[SEQ*DIM],   g_al[SEQ*DIM];
__device__ __align__(256) __nv_bfloat16 g_wqh[DIM*DIM],  g_wql[DIM*DIM];
__device__ __align__(256) __nv_bfloat16 g_wkh[KVDIM*DIM],g_wkl[KVDIM*DIM];
__device__ __align__(256) __nv_bfloat16 g_wvh[KVDIM*DIM],g_wvl[KVDIM*DIM];
__device__ __align__(256) __nv_bfloat16 g_woh[DIM*DIM],  g_wol[DIM*DIM];

// ---------------- packed f32x2 helpers (attention kernel) -------------------
#define PK2(d, lo, hi) \
    asm("mov.b64 %0, {%1, %2};" : "=l"(d) : "r"(__float_as_uint(lo)), "r"(__float_as_uint(hi)))
#define UPK2(lo, hi, d) do { unsigned int _u0, _u1; \
    asm("mov.b64 {%0, %1}, %2;" : "=r"(_u0), "=r"(_u1) : "l"(d)); \
    (lo) = __uint_as_float(_u0); (hi) = __uint_as_float(_u1); } while (0)
#define FMA2(d, a, b) \
    asm("fma.rn.f32x2 %0, %1, %2, %0;" : "+l"(d) : "l"(a), "l"(b))
#define MUL2(d, a, b) \
    asm("mul.rn.f32x2 %0, %1, %2;" : "=l"(d) : "l"(a), "l"(b))

// ---------------- cp.async helpers ------------------------------------------
__device__ __forceinline__ uint smem_u32(const void* p) {
    uint a;
    asm("{ .reg .u64 t; cvta.to.shared.u64 t, %1; cvt.u32.u64 %0, t; }" : "=r"(a) : "l"(p));
    return a;
}
__device__ __forceinline__ void cp16(uint sdst, const void* gsrc) {
    asm volatile("cp.async.cg.shared.global [%0], [%1], 16;" :: "r"(sdst), "l"(gsrc));
}
#define CP_COMMIT() asm volatile("cp.async.commit_group;" ::: "memory")
#define CP_WAIT1()  asm volatile("cp.async.wait_group 1;" ::: "memory")
#define CP_WAIT0()  asm volatile("cp.async.wait_group 0;" ::: "memory")

// ---------------- mma.sync m16n8k16 bf16 -------------------------------------
__device__ __forceinline__ void mma16816(float* d, const uint* a, const uint* b) {
    asm volatile(
        "mma.sync.aligned.m16n8k16.row.col.f32.bf16.bf16.f32 "
        "{%0,%1,%2,%3}, {%4,%5,%6,%7}, {%8,%9}, {%0,%1,%2,%3};"
        : "+f"(d[0]), "+f"(d[1]), "+f"(d[2]), "+f"(d[3])
        : "r"(a[0]), "r"(a[1]), "r"(a[2]), "r"(a[3]), "r"(b[0]), "r"(b[1]));
}

// ---------------- split-bf16 conversion --------------------------------------
__global__ void split_bf16_kernel(const float* __restrict__ in,
                                  __nv_bfloat16* __restrict__ hi,
                                  __nv_bfloat16* __restrict__ lo, int n)
{
    int i = blockIdx.x * blockDim.x + threadIdx.x;
    if (i >= n) return;
    float v = in[i];
    __nv_bfloat16 h = __float2bfloat16(v);
    hi[i] = h;
    lo[i] = __float2bfloat16(v - __bfloat162float(h));
}

// ---------------- HMMA split-bf16 GEMM: C[M,N] = A[M,K] * B[N,K]^T ----------
// C = Ah*Bh^T + Ah*Bl^T + Al*Bh^T, fp32 accum in registers.
// CTA: 128x128 tile, Kc=64, 2-stage cp.async double buffer, 256 threads,
// 8 warps in 2(m) x 4(n), warp tile 64x32 = 4x4 m16n8k16 fragments.
#define TG_THREADS  256
#define TG_PITCH    72                     /* bf16 elems per smem row (144 B) */
#define TG_TILE_B   (128*TG_PITCH*2)       /* 18432 B                          */
#define TG_STAGE_B  (4*TG_TILE_B)          /* Ah, Al, Bh, Bl = 73728 B         */
#define TG_SMEM     (2*TG_STAGE_B)         /* 147456 B                         */

__device__ __forceinline__ void tg_load_stage(
    uint sbase, const __nv_bfloat16* __restrict__ Ah, const __nv_bfloat16* __restrict__ Al,
    const __nv_bfloat16* __restrict__ Bh, const __nv_bfloat16* __restrict__ Bl,
    int m0, int n0, int k0, int K, int tid)
{
    const __nv_bfloat16* srcs[4] = {Ah, Al, Bh, Bl};
#pragma unroll
    for (int t = 0; t < 4; t++) {
        const __nv_bfloat16* s = srcs[t];
        const int r0 = (t < 2) ? m0 : n0;
        const uint tb = sbase + t * TG_TILE_B;
#pragma unroll
        for (int it = 0; it < 4; it++) {
            int cid = it * TG_THREADS + tid;     // 16B chunk id, 0..1023
            int row = cid >> 3;                  // 8 x 16B per row (64 bf16)
            int c16 = cid & 7;
            cp16(tb + row * (TG_PITCH*2) + c16 * 16,
                 s + (size_t)(r0 + row) * K + k0 + c16 * 8);
        }
    }
}

#define LDW(p, row, col) (*(const uint*)((p) + (((row)*TG_PITCH + (col)) << 1)))

__global__ __launch_bounds__(TG_THREADS, 1) void tgemm_bf16s(
    const __nv_bfloat16* __restrict__ Ah, const __nv_bfloat16* __restrict__ Al,
    const __nv_bfloat16* __restrict__ Bh, const __nv_bfloat16* __restrict__ Bl,
    float* __restrict__ C, int M, int N, int K)
{
    extern __shared__ char smem[];
    const uint sb32 = smem_u32(smem);
    const int tid = threadIdx.x;
    const int lane = tid & 31, wid = tid >> 5;
    const int warp_m = wid & 1, warp_n = wid >> 1;
    const int mbase = warp_m * 64, nbase = warp_n * 32;
    const int g = lane >> 2, t4 = lane & 3;
    const int m0 = blockIdx.y * 128, n0 = blockIdx.x * 128;

    float acc[4][4][4];
#pragma unroll
    for (int i = 0; i < 4; i++)
#pragma unroll
        for (int j = 0; j < 4; j++)
#pragma unroll
            for (int k = 0; k < 4; k++) acc[i][j][k] = 0.0f;

    const int nch = K >> 6;
    tg_load_stage(sb32, Ah, Al, Bh, Bl, m0, n0, 0, K, tid);
    CP_COMMIT();

    for (int ch = 0; ch < nch; ch++) {
        if (ch + 1 < nch) {
            tg_load_stage(sb32 + ((ch + 1) & 1) * TG_STAGE_B,
                          Ah, Al, Bh, Bl, m0, n0, (ch + 1) << 6, K, tid);
            CP_COMMIT();
            CP_WAIT1();
        } else {
            CP_WAIT0();
        }
        __syncthreads();

        const char* st  = smem + (ch & 1) * TG_STAGE_B;
        const char* pAh = st;
        const char* pAl = st + TG_TILE_B;
        const char* pBh = st + 2 * TG_TILE_B;
        const char* pBl = st + 3 * TG_TILE_B;

#pragma unroll
        for (int ks = 0; ks < 4; ks++) {
            const int kc = ks * 16 + t4 * 2;
            uint ah[4][4], al[4][4], bh[4][2], bl[4][2];
#pragma unroll
            for (int mt = 0; mt < 4; mt++) {
                int r = mbase + mt * 16 + g;
                ah[mt][0] = LDW(pAh, r,     kc);
                ah[mt][1] = LDW(pAh, r + 8, kc);
                ah[mt][2] = LDW(pAh, r,     kc + 8);
                ah[mt][3] = LDW(pAh, r + 8, kc + 8);
                al[mt][0] = LDW(pAl, r,     kc);
                al[mt][1] = LDW(pAl, r + 8, kc);
                al[mt][2] = LDW(pAl, r,     kc + 8);
                al[mt][3] = LDW(pAl, r + 8, kc + 8);
            }
#pragma unroll
            for (int nt = 0; nt < 4; nt++) {
                int nr = nbase + nt * 8 + g;
                bh[nt][0] = LDW(pBh, nr, kc);
                bh[nt][1] = LDW(pBh, nr, kc + 8);
                bl[nt][0] = LDW(pBl, nr, kc);
                bl[nt][1] = LDW(pBl, nr, kc + 8);
            }
#pragma unroll
            for (int mt = 0; mt < 4; mt++)
#pragma unroll
                for (int nt = 0; nt < 4; nt++) {
                    mma16816(acc[mt][nt], ah[mt], bh[nt]);
                    mma16816(acc[mt][nt], ah[mt], bl[nt]);
                    mma16816(acc[mt][nt], al[mt], bh[nt]);
                }
        }
        __syncthreads();
    }

    // epilogue: fragment layout -> C
#pragma unroll
    for (int mt = 0; mt < 4; mt++)
#pragma unroll
        for (int nt = 0; nt < 4; nt++) {
            int r = m0 + mbase + mt * 16 + g;
            int c = n0 + nbase + nt * 8 + t4 * 2;
            float2 v0 = {acc[mt][nt][0], acc[mt][nt][1]};
            float2 v1 = {acc[mt][nt][2], acc[mt][nt][3]};
            *(float2*)&C[(size_t)r * N + c]       = v0;
            *(float2*)&C[(size_t)(r + 8) * N + c] = v1;
        }
}

// ---------------- RoPE table + apply ----------------------------------------
__global__ void rope_tab_kernel(float* __restrict__ cosT, float* __restrict__ sinT)
{
    int idx = blockIdx.x * blockDim.x + threadIdx.x;
    if (idx >= SEQ * (HD/2)) return;
    int s = idx / (HD/2);
    int i = idx % (HD/2);
    double freq = pow(500000.0, -(double)(2*i) / (double)HD);
    float ff = (float)freq;
    float ang = (float)s * ff;
    cosT[idx] = (float)cos((double)ang);
    sinT[idx] = (float)sin((double)ang);
}

__global__ void rope_apply_kernel(float* __restrict__ X,
                                  const float* __restrict__ cosT,
                                  const float* __restrict__ sinT, int nheads)
{
    int idx = blockIdx.x * blockDim.x + threadIdx.x;
    int total = SEQ * nheads * (HD/2);
    if (idx >= total) return;
    int i = idx % (HD/2);
    int h = (idx / (HD/2)) % nheads;
    int s = idx / ((HD/2) * nheads);
    float c  = cosT[s*(HD/2) + i];
    float sn = sinT[s*(HD/2) + i];
    float* p = X + (size_t)s * (nheads*HD) + h*HD + 2*i;
    float e = p[0], o = p[1];
    p[0] = e*c - o*sn;
    p[1] = e*sn + o*c;
}

// ---------------- Flash attention (fp32, online softmax, causal, GQA) -------
#define ATTN_SMEM ((128*64 + 128*64 + 64*128 + 64*65) * 4)

__global__ __launch_bounds__(256) void attn_kernel(
    const float* __restrict__ Q, const float* __restrict__ K,
    const float* __restrict__ V, float* __restrict__ O)
{
    extern __shared__ float sm[];
    float* QsT = sm;
    float* KsT = QsT + 128*64;
    float* Vs  = KsT + 128*64;
    float* Ps  = Vs  + 64*128;

    const int tid = threadIdx.x;
    const int tx = tid & 15, ty = tid >> 4;
    const int qb = blockIdx.x, h = blockIdx.y;
    const int kvh = h >> 2;
    const int q0 = qb * 64;
    const float scale = 0.08838834764831845f;

#pragma unroll
    for (int it = 0; it < 8; it++) {
        int lin = it * 1024 + tid * 4;
        int r = lin >> 7, c = lin & 127;
        float4 v = *(const float4*)&Q[(size_t)(q0 + r)*DIM + h*HD + c];
        QsT[(c+0)*64 + r] = v.x; QsT[(c+1)*64 + r] = v.y;
        QsT[(c+2)*64 + r] = v.z; QsT[(c+3)*64 + r] = v.w;
    }

    float m[4], l[4];
    ull Oa[4][4];
#pragma unroll
    for (int i = 0; i < 4; i++) {
        m[i] = -INFINITY; l[i] = 0.0f;
#pragma unroll
        for (int j = 0; j < 4; j++) Oa[i][j] = 0ULL;
    }

    for (int kb = 0; kb <= qb; kb++) {
        __syncthreads();
        const int k0 = kb * 64;
#pragma unroll
        for (int it = 0; it < 8; it++) {
            int lin = it * 1024 + tid * 4;
            int r = lin >> 7, c = lin & 127;
            float4 kv4 = *(const float4*)&K[(size_t)(k0 + r)*KVDIM + kvh*HD + c];
            KsT[(c+0)*64 + r] = kv4.x; KsT[(c+1)*64 + r] = kv4.y;
            KsT[(c+2)*64 + r] = kv4.z; KsT[(c+3)*64 + r] = kv4.w;
            float4 vv4 = *(const float4*)&V[(size_t)(k0 + r)*KVDIM + kvh*HD + c];
            *(float4*)&Vs[r*128 + c] = vv4;
        }
        __syncthreads();

        ull sa[4][2];
#pragma unroll
        for (int i = 0; i < 4; i++) { sa[i][0] = 0ULL; sa[i][1] = 0ULL; }
#pragma unroll 4
        for (int d = 0; d < 128; d++) {
            float4 a = *(const float4*)&QsT[d*64 + ty*4];
            float4 b = *(const float4*)&KsT[d*64 + tx*4];
            ull b01, b23; PK2(b01, b.x, b.y); PK2(b23, b.z, b.w);
            float aa[4] = {a.x, a.y, a.z, a.w};
#pragma unroll
            for (int i = 0; i < 4; i++) {
                ull ad; PK2(ad, aa[i], aa[i]);
                FMA2(sa[i][0], ad, b01);
                FMA2(sa[i][1], ad, b23);
            }
        }
        float s[4][4];
#pragma unroll
        for (int i = 0; i < 4; i++) {
            UPK2(s[i][0], s[i][1], sa[i][0]);
            UPK2(s[i][2], s[i][3], sa[i][1]);
        }

        const bool diag = (kb == qb);
#pragma unroll
        for (int i = 0; i < 4; i++)
#pragma unroll
            for (int j = 0; j < 4; j++) {
                s[i][j] *= scale;
                if (diag && (tx*4 + j) > (ty*4 + i)) s[i][j] = -INFINITY;
            }

#pragma unroll
        for (int i = 0; i < 4; i++) {
            float v = fmaxf(fmaxf(s[i][0], s[i][1]), fmaxf(s[i][2], s[i][3]));
#pragma unroll
            for (int off = 8; off >= 1; off >>= 1)
                v = fmaxf(v, __shfl_xor_sync(0xffffffffu, v, off));
            float mn = fmaxf(m[i], v);

            float p0 = expf(s[i][0] - mn), p1 = expf(s[i][1] - mn);
            float p2 = expf(s[i][2] - mn), p3 = expf(s[i][3] - mn);
            s[i][0] = p0; s[i][1] = p1; s[i][2] = p2; s[i][3] = p3;
            float ls = p0 + p1 + p2 + p3;
#pragma unroll
            for (int off = 8; off >= 1; off >>= 1)
                ls += __shfl_xor_sync(0xffffffffu, ls, off);

            float alpha = expf(m[i] - mn);
            l[i] = l[i] * alpha + ls;
            m[i] = mn;
            ull am; PK2(am, alpha, alpha);
#pragma unroll
            for (int j = 0; j < 4; j++) { ull t; MUL2(t, Oa[i][j], am); Oa[i][j] = t; }
        }

#pragma unroll
        for (int i = 0; i < 4; i++)
#pragma unroll
            for (int j = 0; j < 4; j++)
                Ps[(ty*4 + i)*65 + tx*4 + j] = s[i][j];
        __syncthreads();

#pragma unroll 2
        for (int kk = 0; kk < 64; kk++) {
            float4 v0 = *(const float4*)&Vs[kk*128 + tx*8];
            float4 v1 = *(const float4*)&Vs[kk*128 + tx*8 + 4];
            ull vv[4];
            PK2(vv[0], v0.x, v0.y); PK2(vv[1], v0.z, v0.w);
            PK2(vv[2], v1.x, v1.y); PK2(vv[3], v1.z, v1.w);
#pragma unroll
            for (int i = 0; i < 4; i++) {
                float p = Ps[(ty*4 + i)*65 + kk];
                ull pd; PK2(pd, p, p);
#pragma unroll
                for (int j = 0; j < 4; j++) FMA2(Oa[i][j], pd, vv[j]);
            }
        }
    }

#pragma unroll
    for (int i = 0; i < 4; i++) {
        float inv = 1.0f / l[i];
        float4 o0, o1;
        UPK2(o0.x, o0.y, Oa[i][0]); UPK2(o0.z, o0.w, Oa[i][1]);
        UPK2(o1.x, o1.y, Oa[i][2]); UPK2(o1.z, o1.w, Oa[i][3]);
        o0.x *= inv; o0.y *= inv; o0.z *= inv; o0.w *= inv;
        o1.x *= inv; o1.y *= inv; o1.z *= inv; o1.w *= inv;
        float* Op = O + (size_t)(q0 + ty*4 + i)*DIM + h*HD + tx*8;
        *(float4*)Op = o0;
        *(float4*)(Op + 4) = o1;
    }
}

// ---------------- launch -----------------------------------------------------
extern "C" void kernel_launch(void* const* d_in, const int* in_sizes, int n_in,
                              void* d_out, int out_size)
{
    const float* x  = (const float*)d_in[0];
    const float* wq = (const float*)d_in[1];
    const float* wk = (const float*)d_in[2];
    const float* wv = (const float*)d_in[3];
    const float* wo = (const float*)d_in[4];
    float* out = (float*)d_out;

    float *Qp, *Kp, *Vp, *Ap, *cp, *sp;
    cudaGetSymbolAddress((void**)&Qp, g_Q);
    cudaGetSymbolAddress((void**)&Kp, g_K);
    cudaGetSymbolAddress((void**)&Vp, g_V);
    cudaGetSymbolAddress((void**)&Ap, g_attn);
    cudaGetSymbolAddress((void**)&cp, g_cos);
    cudaGetSymbolAddress((void**)&sp, g_sin);

    __nv_bfloat16 *xh,*xl,*ah,*al,*wqh,*wql,*wkh,*wkl,*wvh,*wvl,*woh,*wol;
    cudaGetSymbolAddress((void**)&xh,  g_xh);  cudaGetSymbolAddress((void**)&xl,  g_xl);
    cudaGetSymbolAddress((void**)&ah,  g_ah);  cudaGetSymbolAddress((void**)&al,  g_al);
    cudaGetSymbolAddress((void**)&wqh, g_wqh); cudaGetSymbolAddress((void**)&wql, g_wql);
    cudaGetSymbolAddress((void**)&wkh, g_wkh); cudaGetSymbolAddress((void**)&wkl, g_wkl);
    cudaGetSymbolAddress((void**)&wvh, g_wvh); cudaGetSymbolAddress((void**)&wvl, g_wvl);
    cudaGetSymbolAddress((void**)&woh, g_woh); cudaGetSymbolAddress((void**)&wol, g_wol);

    cudaFuncSetAttribute(attn_kernel, cudaFuncAttributeMaxDynamicSharedMemorySize, ATTN_SMEM);
    cudaFuncSetAttribute(tgemm_bf16s, cudaFuncAttributeMaxDynamicSharedMemorySize, TG_SMEM);

    rope_tab_kernel<<<(SEQ*(HD/2) + 255)/256, 256>>>(cp, sp);

    // split inputs/weights to bf16 hi/lo
    split_bf16_kernel<<<(SEQ*DIM + 255)/256, 256>>>(x,  xh,  xl,  SEQ*DIM);
    split_bf16_kernel<<<(DIM*DIM + 255)/256, 256>>>(wq, wqh, wql, DIM*DIM);
    split_bf16_kernel<<<(KVDIM*DIM + 255)/256, 256>>>(wk, wkh, wkl, KVDIM*DIM);
    split_bf16_kernel<<<(KVDIM*DIM + 255)/256, 256>>>(wv, wvh, wvl, KVDIM*DIM);
    split_bf16_kernel<<<(DIM*DIM + 255)/256, 256>>>(wo, woh, wol, DIM*DIM);

    // projections on tensor cores (HMMA)
    tgemm_bf16s<<<dim3(DIM/128,   SEQ/128), TG_THREADS, TG_SMEM>>>(xh, xl, wqh, wql, Qp, SEQ, DIM,   DIM);
    tgemm_bf16s<<<dim3(KVDIM/128, SEQ/128), TG_THREADS, TG_SMEM>>>(xh, xl, wkh, wkl, Kp, SEQ, KVDIM, DIM);
    tgemm_bf16s<<<dim3(KVDIM/128, SEQ/128), TG_THREADS, TG_SMEM>>>(xh, xl, wvh, wvl, Vp, SEQ, KVDIM, DIM);

    rope_apply_kernel<<<(SEQ*NH*(HD/2))/256,   256>>>(Qp, cp, sp, NH);
    rope_apply_kernel<<<(SEQ*NKVH*(HD/2))/256, 256>>>(Kp, cp, sp, NKVH);

    attn_kernel<<<dim3(SEQ/64, NH), 256, ATTN_SMEM>>>(Qp, Kp, Vp, Ap);

    // output projection on tensor cores (HMMA)
    split_bf16_kernel<<<(SEQ*DIM + 255)/256, 256>>>(Ap, ah, al, SEQ*DIM);
    tgemm_bf16s<<<dim3(DIM/128, SEQ/128), TG_THREADS, TG_SMEM>>>(ah, al, woh, wol, out, SEQ, DIM, DIM);
}

// round 12
// speedup vs baseline: 2.9282x; 1.6504x over previous
#include <cuda_runtime.h>
#include <cuda_bf16.h>
#include <math.h>

#define SEQ   2048
#define DIM   4096
#define NH    32
#define NKVH  8
#define HD    128
#define KVDIM (NKVH*HD)   /* 1024 */

typedef unsigned long long ull;
typedef unsigned int uint;

// ---------------- scratch (device globals: no allocation allowed) -----------
__device__ __align__(256) float g_Q[SEQ*DIM];
__device__ __align__(256) float g_K[SEQ*KVDIM];
__device__ __align__(256) float g_V[SEQ*KVDIM];
__device__ __align__(256) float g_attn[SEQ*DIM];
__device__ __align__(256) float g_cos[SEQ*(HD/2)];
__device__ __align__(256) float g_sin[SEQ*(HD/2)];
// split-bf16 operands (projection GEMMs)
__device__ __align__(256) __nv_bfloat16 g_xh[SEQ*DIM],   g_xl[SEQ*DIM];
__device__ __align__(256) __nv_bfloat16 g_ah[SEQ*DIM],   g_al[SEQ*DIM];
__device__ __align__(256) __nv_bfloat16 g_wqh[DIM*DIM],  g_wql[DIM*DIM];
__device__ __align__(256) __nv_bfloat16 g_wkh[KVDIM*DIM],g_wkl[KVDIM*DIM];
__device__ __align__(256) __nv_bfloat16 g_wvh[KVDIM*DIM],g_wvl[KVDIM*DIM];
__device__ __align__(256) __nv_bfloat16 g_woh[DIM*DIM],  g_wol[DIM*DIM];
// split-bf16 operands (attention)
__device__ __align__(256) __nv_bfloat16 g_qsh[SEQ*DIM],   g_qsl[SEQ*DIM];
__device__ __align__(256) __nv_bfloat16 g_ksh[SEQ*KVDIM], g_ksl[SEQ*KVDIM];
__device__ __align__(256) __nv_bfloat16 g_vth[KVDIM*SEQ], g_vtl[KVDIM*SEQ];

// ---------------- cp.async helpers ------------------------------------------
__device__ __forceinline__ uint smem_u32(const void* p) {
    uint a;
    asm("{ .reg .u64 t; cvta.to.shared.u64 t, %1; cvt.u32.u64 %0, t; }" : "=r"(a) : "l"(p));
    return a;
}
__device__ __forceinline__ void cp16(uint sdst, const void* gsrc) {
    asm volatile("cp.async.cg.shared.global [%0], [%1], 16;" :: "r"(sdst), "l"(gsrc));
}
#define CP_COMMIT() asm volatile("cp.async.commit_group;" ::: "memory")
#define CP_WAIT1()  asm volatile("cp.async.wait_group 1;" ::: "memory")
#define CP_WAIT0()  asm volatile("cp.async.wait_group 0;" ::: "memory")

// ---------------- mma.sync m16n8k16 bf16 (HW-validated in R11) ---------------
__device__ __forceinline__ void mma16816(float* d, const uint* a, const uint* b) {
    asm volatile(
        "mma.sync.aligned.m16n8k16.row.col.f32.bf16.bf16.f32 "
        "{%0,%1,%2,%3}, {%4,%5,%6,%7}, {%8,%9}, {%0,%1,%2,%3};"
        : "+f"(d[0]), "+f"(d[1]), "+f"(d[2]), "+f"(d[3])
        : "r"(a[0]), "r"(a[1]), "r"(a[2]), "r"(a[3]), "r"(b[0]), "r"(b[1]));
}

__device__ __forceinline__ uint packbf(float lo, float hi) {
    uint r;
    asm("cvt.rn.bf16x2.f32 %0, %1, %2;" : "=r"(r) : "f"(hi), "f"(lo));
    return r;
}

// ---------------- split-bf16 conversion --------------------------------------
__global__ void split_bf16_kernel(const float* __restrict__ in,
                                  __nv_bfloat16* __restrict__ hi,
                                  __nv_bfloat16* __restrict__ lo, int n)
{
    int i = blockIdx.x * blockDim.x + threadIdx.x;
    if (i >= n) return;
    float v = in[i];
    __nv_bfloat16 h = __float2bfloat16(v);
    hi[i] = h;
    lo[i] = __float2bfloat16(v - __bfloat162float(h));
}

// split V and transpose to [channel][seq] (channel = kvh*HD + d)
__global__ void vt_split_kernel(const float* __restrict__ V,
                                __nv_bfloat16* __restrict__ vth,
                                __nv_bfloat16* __restrict__ vtl)
{
    int idx = blockIdx.x * blockDim.x + threadIdx.x;   // 0..KVDIM*SEQ-1
    int s = idx & (SEQ - 1);
    int c = idx >> 11;                                  // SEQ = 2048
    float v = V[(size_t)s * KVDIM + c];
    __nv_bfloat16 h = __float2bfloat16(v);
    vth[idx] = h;
    vtl[idx] = __float2bfloat16(v - __bfloat162float(h));
}

// ---------------- HMMA split-bf16 GEMM (unchanged, validated R11) ------------
#define TG_THREADS  256
#define TG_PITCH    72
#define TG_TILE_B   (128*TG_PITCH*2)
#define TG_STAGE_B  (4*TG_TILE_B)
#define TG_SMEM     (2*TG_STAGE_B)

__device__ __forceinline__ void tg_load_stage(
    uint sbase, const __nv_bfloat16* __restrict__ Ah, const __nv_bfloat16* __restrict__ Al,
    const __nv_bfloat16* __restrict__ Bh, const __nv_bfloat16* __restrict__ Bl,
    int m0, int n0, int k0, int K, int tid)
{
    const __nv_bfloat16* srcs[4] = {Ah, Al, Bh, Bl};
#pragma unroll
    for (int t = 0; t < 4; t++) {
        const __nv_bfloat16* s = srcs[t];
        const int r0 = (t < 2) ? m0 : n0;
        const uint tb = sbase + t * TG_TILE_B;
#pragma unroll
        for (int it = 0; it < 4; it++) {
            int cid = it * TG_THREADS + tid;
            int row = cid >> 3;
            int c16 = cid & 7;
            cp16(tb + row * (TG_PITCH*2) + c16 * 16,
                 s + (size_t)(r0 + row) * K + k0 + c16 * 8);
        }
    }
}

#define LDW(p, row, col) (*(const uint*)((p) + (((row)*TG_PITCH + (col)) << 1)))

__global__ __launch_bounds__(TG_THREADS, 1) void tgemm_bf16s(
    const __nv_bfloat16* __restrict__ Ah, const __nv_bfloat16* __restrict__ Al,
    const __nv_bfloat16* __restrict__ Bh, const __nv_bfloat16* __restrict__ Bl,
    float* __restrict__ C, int M, int N, int K)
{
    extern __shared__ char smem[];
    const uint sb32 = smem_u32(smem);
    const int tid = threadIdx.x;
    const int lane = tid & 31, wid = tid >> 5;
    const int warp_m = wid & 1, warp_n = wid >> 1;
    const int mbase = warp_m * 64, nbase = warp_n * 32;
    const int g = lane >> 2, t4 = lane & 3;
    const int m0 = blockIdx.y * 128, n0 = blockIdx.x * 128;

    float acc[4][4][4];
#pragma unroll
    for (int i = 0; i < 4; i++)
#pragma unroll
        for (int j = 0; j < 4; j++)
#pragma unroll
            for (int k = 0; k < 4; k++) acc[i][j][k] = 0.0f;

    const int nch = K >> 6;
    tg_load_stage(sb32, Ah, Al, Bh, Bl, m0, n0, 0, K, tid);
    CP_COMMIT();

    for (int ch = 0; ch < nch; ch++) {
        if (ch + 1 < nch) {
            tg_load_stage(sb32 + ((ch + 1) & 1) * TG_STAGE_B,
                          Ah, Al, Bh, Bl, m0, n0, (ch + 1) << 6, K, tid);
            CP_COMMIT();
            CP_WAIT1();
        } else {
            CP_WAIT0();
        }
        __syncthreads();

        const char* st  = smem + (ch & 1) * TG_STAGE_B;
        const char* pAh = st;
        const char* pAl = st + TG_TILE_B;
        const char* pBh = st + 2 * TG_TILE_B;
        const char* pBl = st + 3 * TG_TILE_B;

#pragma unroll
        for (int ks = 0; ks < 4; ks++) {
            const int kc = ks * 16 + t4 * 2;
            uint ah[4][4], al[4][4], bh[4][2], bl[4][2];
#pragma unroll
            for (int mt = 0; mt < 4; mt++) {
                int r = mbase + mt * 16 + g;
                ah[mt][0] = LDW(pAh, r,     kc);
                ah[mt][1] = LDW(pAh, r + 8, kc);
                ah[mt][2] = LDW(pAh, r,     kc + 8);
                ah[mt][3] = LDW(pAh, r + 8, kc + 8);
                al[mt][0] = LDW(pAl, r,     kc);
                al[mt][1] = LDW(pAl, r + 8, kc);
                al[mt][2] = LDW(pAl, r,     kc + 8);
                al[mt][3] = LDW(pAl, r + 8, kc + 8);
            }
#pragma unroll
            for (int nt = 0; nt < 4; nt++) {
                int nr = nbase + nt * 8 + g;
                bh[nt][0] = LDW(pBh, nr, kc);
                bh[nt][1] = LDW(pBh, nr, kc + 8);
                bl[nt][0] = LDW(pBl, nr, kc);
                bl[nt][1] = LDW(pBl, nr, kc + 8);
            }
#pragma unroll
            for (int mt = 0; mt < 4; mt++)
#pragma unroll
                for (int nt = 0; nt < 4; nt++) {
                    mma16816(acc[mt][nt], ah[mt], bh[nt]);
                    mma16816(acc[mt][nt], ah[mt], bl[nt]);
                    mma16816(acc[mt][nt], al[mt], bh[nt]);
                }
        }
        __syncthreads();
    }

#pragma unroll
    for (int mt = 0; mt < 4; mt++)
#pragma unroll
        for (int nt = 0; nt < 4; nt++) {
            int r = m0 + mbase + mt * 16 + g;
            int c = n0 + nbase + nt * 8 + t4 * 2;
            float2 v0 = {acc[mt][nt][0], acc[mt][nt][1]};
            float2 v1 = {acc[mt][nt][2], acc[mt][nt][3]};
            *(float2*)&C[(size_t)r * N + c]       = v0;
            *(float2*)&C[(size_t)(r + 8) * N + c] = v1;
        }
}

// ---------------- RoPE table + apply ----------------------------------------
__global__ void rope_tab_kernel(float* __restrict__ cosT, float* __restrict__ sinT)
{
    int idx = blockIdx.x * blockDim.x + threadIdx.x;
    if (idx >= SEQ * (HD/2)) return;
    int s = idx / (HD/2);
    int i = idx % (HD/2);
    double freq = pow(500000.0, -(double)(2*i) / (double)HD);
    float ff = (float)freq;
    float ang = (float)s * ff;
    cosT[idx] = (float)cos((double)ang);
    sinT[idx] = (float)sin((double)ang);
}

__global__ void rope_apply_kernel(float* __restrict__ X,
                                  const float* __restrict__ cosT,
                                  const float* __restrict__ sinT, int nheads)
{
    int idx = blockIdx.x * blockDim.x + threadIdx.x;
    int total = SEQ * nheads * (HD/2);
    if (idx >= total) return;
    int i = idx % (HD/2);
    int h = (idx / (HD/2)) % nheads;
    int s = idx / ((HD/2) * nheads);
    float c  = cosT[s*(HD/2) + i];
    float sn = sinT[s*(HD/2) + i];
    float* p = X + (size_t)s * (nheads*HD) + h*HD + 2*i;
    float e = p[0], o = p[1];
    p[0] = e*c - o*sn;
    p[1] = e*sn + o*c;
}

// ---------------- HMMA flash attention (split-bf16, causal, GQA) ------------
// CTA: 128 q-rows x 1 head; 8 warps, each m16 x all-k; K/VT double-buffered.
// SMEM layout (bytes): Qh 0, Ql 34816 (pitch 272, 128 rows);
// stage s at 69632 + s*71680: Kh +0, Kl +17408 (pitch 272, 64 rows),
//                             VTh +34816, VTl +53248 (pitch 144, 128 rows).
#define AT_SMEM  212992
#define QP 272
#define VP 144

__device__ __forceinline__ void at_load_kv(
    uint stage, const __nv_bfloat16* __restrict__ Kh, const __nv_bfloat16* __restrict__ Kl,
    const __nv_bfloat16* __restrict__ VTh, const __nv_bfloat16* __restrict__ VTl,
    int k0, int kvh, int tid)
{
#pragma unroll
    for (int it = 0; it < 8; it++) {
        int cid = it * 256 + tid;
        int tile = cid >> 10, c2 = cid & 1023;
        int r = c2 >> 4, c = c2 & 15;
        const __nv_bfloat16* src = (tile ? Kl : Kh) + (size_t)(k0 + r) * KVDIM + kvh * HD + c * 8;
        cp16(stage + tile * 17408 + r * QP + c * 16, src);
    }
#pragma unroll
    for (int it = 0; it < 8; it++) {
        int cid = it * 256 + tid;
        int tile = cid >> 10, c2 = cid & 1023;
        int r = c2 >> 3, c = c2 & 7;
        const __nv_bfloat16* src = (tile ? VTl : VTh) + (size_t)(kvh * HD + r) * SEQ + k0 + c * 8;
        cp16(stage + 34816 + tile * 18432 + r * VP + c * 16, src);
    }
}

__global__ __launch_bounds__(256, 1) void attn_hmma(
    const __nv_bfloat16* __restrict__ Qh, const __nv_bfloat16* __restrict__ Ql,
    const __nv_bfloat16* __restrict__ Kh, const __nv_bfloat16* __restrict__ Kl,
    const __nv_bfloat16* __restrict__ VTh, const __nv_bfloat16* __restrict__ VTl,
    float* __restrict__ O)
{
    extern __shared__ char sm_[];
    const uint sb = smem_u32(sm_);
    const int tid = threadIdx.x, lane = tid & 31, wid = tid >> 5;
    const int g = lane >> 2, t4 = lane & 3;
    const int qb = (int)gridDim.x - 1 - (int)blockIdx.x;   // heavy CTAs first
    const int q0 = qb * 128;
    const int h = blockIdx.y, kvh = h >> 2;
    const int nkb = 2 * qb + 2;
    const float scale = 0.08838834764831845f;
    const int row0 = wid * 16 + g;

    // Q tiles (in commit-group 0 together with stage 0)
#pragma unroll
    for (int it = 0; it < 16; it++) {
        int cid = it * 256 + tid;
        int tile = cid >> 11, c2 = cid & 2047;
        int r = c2 >> 4, c = c2 & 15;
        const __nv_bfloat16* src = (tile ? Ql : Qh) + (size_t)(q0 + r) * DIM + h * HD + c * 8;
        cp16(sb + tile * 34816 + r * QP + c * 16, src);
    }
    at_load_kv(sb + 69632, Kh, Kl, VTh, VTl, 0, kvh, tid);
    CP_COMMIT();

    float m0v = -INFINITY, m1v = -INFINITY, l0v = 0.0f, l1v = 0.0f;
    float oacc[16][4];
#pragma unroll
    for (int i = 0; i < 16; i++)
#pragma unroll
        for (int j = 0; j < 4; j++) oacc[i][j] = 0.0f;

    for (int kb = 0; kb < nkb; kb++) {
        if (kb + 1 < nkb) {
            at_load_kv(sb + 69632 + ((kb + 1) & 1) * 71680, Kh, Kl, VTh, VTl,
                       (kb + 1) * 64, kvh, tid);
            CP_COMMIT();
            CP_WAIT1();
        } else {
            CP_WAIT0();
        }
        __syncthreads();

        const char* pqh = sm_;
        const char* pql = sm_ + 34816;
        const char* pst = sm_ + 69632 + (size_t)(kb & 1) * 71680;
        const char* pkh = pst;
        const char* pkl = pst + 17408;
        const char* pvh = pst + 34816;
        const char* pvl = pst + 53248;

        // ---- S = Q K^T (3 split passes) ----
        float sacc[8][4];
#pragma unroll
        for (int i = 0; i < 8; i++)
#pragma unroll
            for (int j = 0; j < 4; j++) sacc[i][j] = 0.0f;

#pragma unroll
        for (int ks = 0; ks < 8; ks++) {
            const int qw = ks * 8 + t4;
            uint qa_h[4], qa_l[4];
            qa_h[0] = *(const uint*)(pqh + (row0    ) * QP + qw * 4);
            qa_h[1] = *(const uint*)(pqh + (row0 + 8) * QP + qw * 4);
            qa_h[2] = *(const uint*)(pqh + (row0    ) * QP + (qw + 4) * 4);
            qa_h[3] = *(const uint*)(pqh + (row0 + 8) * QP + (qw + 4) * 4);
            qa_l[0] = *(const uint*)(pql + (row0    ) * QP + qw * 4);
            qa_l[1] = *(const uint*)(pql + (row0 + 8) * QP + qw * 4);
            qa_l[2] = *(const uint*)(pql + (row0    ) * QP + (qw + 4) * 4);
            qa_l[3] = *(const uint*)(pql + (row0 + 8) * QP + (qw + 4) * 4);
#pragma unroll
            for (int nt = 0; nt < 8; nt++) {
                const int kr = nt * 8 + g;
                uint kb_h[2], kb_l[2];
                kb_h[0] = *(const uint*)(pkh + kr * QP + qw * 4);
                kb_h[1] = *(const uint*)(pkh + kr * QP + (qw + 4) * 4);
                kb_l[0] = *(const uint*)(pkl + kr * QP + qw * 4);
                kb_l[1] = *(const uint*)(pkl + kr * QP + (qw + 4) * 4);
                mma16816(sacc[nt], qa_h, kb_h);
                mma16816(sacc[nt], qa_h, kb_l);
                mma16816(sacc[nt], qa_l, kb_h);
            }
        }

        // ---- scale + causal mask + online softmax ----
        const int k0 = kb * 64;
        const bool diag = (kb >= nkb - 2);
#pragma unroll
        for (int nt = 0; nt < 8; nt++)
#pragma unroll
            for (int c = 0; c < 4; c++) {
                float v = sacc[nt][c] * scale;
                if (diag) {
                    int col  = k0 + nt * 8 + t4 * 2 + (c & 1);
                    int grow = q0 + row0 + ((c >> 1) << 3);
                    if (col > grow) v = -INFINITY;
                }
                sacc[nt][c] = v;
            }

        float vm0 = -INFINITY, vm1 = -INFINITY;
#pragma unroll
        for (int nt = 0; nt < 8; nt++) {
            vm0 = fmaxf(vm0, fmaxf(sacc[nt][0], sacc[nt][1]));
            vm1 = fmaxf(vm1, fmaxf(sacc[nt][2], sacc[nt][3]));
        }
        vm0 = fmaxf(vm0, __shfl_xor_sync(0xffffffffu, vm0, 1));
        vm0 = fmaxf(vm0, __shfl_xor_sync(0xffffffffu, vm0, 2));
        vm1 = fmaxf(vm1, __shfl_xor_sync(0xffffffffu, vm1, 1));
        vm1 = fmaxf(vm1, __shfl_xor_sync(0xffffffffu, vm1, 2));

        const float mn0 = fmaxf(m0v, vm0);
        const float mn1 = fmaxf(m1v, vm1);
        float ls0 = 0.0f, ls1 = 0.0f;
#pragma unroll
        for (int nt = 0; nt < 8; nt++) {
            float p0 = expf(sacc[nt][0] - mn0);
            float p1 = expf(sacc[nt][1] - mn0);
            float p2 = expf(sacc[nt][2] - mn1);
            float p3 = expf(sacc[nt][3] - mn1);
            sacc[nt][0] = p0; sacc[nt][1] = p1; sacc[nt][2] = p2; sacc[nt][3] = p3;
            ls0 += p0 + p1; ls1 += p2 + p3;
        }
        ls0 += __shfl_xor_sync(0xffffffffu, ls0, 1);
        ls0 += __shfl_xor_sync(0xffffffffu, ls0, 2);
        ls1 += __shfl_xor_sync(0xffffffffu, ls1, 1);
        ls1 += __shfl_xor_sync(0xffffffffu, ls1, 2);

        const float a0 = expf(m0v - mn0);
        const float a1 = expf(m1v - mn1);
        l0v = l0v * a0 + ls0;
        l1v = l1v * a1 + ls1;
        m0v = mn0; m1v = mn1;
#pragma unroll
        for (int dt = 0; dt < 16; dt++) {
            oacc[dt][0] *= a0; oacc[dt][1] *= a0;
            oacc[dt][2] *= a1; oacc[dt][3] *= a1;
        }

        // ---- O += P V (P re-packed from S fragments, split in-register) ----
#pragma unroll
        for (int j = 0; j < 4; j++) {
            const float* sA = sacc[2 * j];
            const float* sB = sacc[2 * j + 1];
            uint pa_h[4], pa_l[4];
            pa_h[0] = packbf(sA[0], sA[1]);
            pa_h[1] = packbf(sA[2], sA[3]);
            pa_h[2] = packbf(sB[0], sB[1]);
            pa_h[3] = packbf(sB[2], sB[3]);
            pa_l[0] = packbf(sA[0] - __uint_as_float(pa_h[0] << 16),
                             sA[1] - __uint_as_float(pa_h[0] & 0xFFFF0000u));
            pa_l[1] = packbf(sA[2] - __uint_as_float(pa_h[1] << 16),
                             sA[3] - __uint_as_float(pa_h[1] & 0xFFFF0000u));
            pa_l[2] = packbf(sB[0] - __uint_as_float(pa_h[2] << 16),
                             sB[1] - __uint_as_float(pa_h[2] & 0xFFFF0000u));
            pa_l[3] = packbf(sB[2] - __uint_as_float(pa_h[3] << 16),
                             sB[3] - __uint_as_float(pa_h[3] & 0xFFFF0000u));
            const int vw = j * 8 + t4;
#pragma unroll
            for (int dt = 0; dt < 16; dt++) {
                const int vr = dt * 8 + g;
                uint vb_h[2], vb_l[2];
                vb_h[0] = *(const uint*)(pvh + vr * VP + vw * 4);
                vb_h[1] = *(const uint*)(pvh + vr * VP + (vw + 4) * 4);
                vb_l[0] = *(const uint*)(pvl + vr * VP + vw * 4);
                vb_l[1] = *(const uint*)(pvl + vr * VP + (vw + 4) * 4);
                mma16816(oacc[dt], pa_h, vb_h);
                mma16816(oacc[dt], pa_h, vb_l);
                mma16816(oacc[dt], pa_l, vb_h);
            }
        }
        __syncthreads();   // before next iteration overwrites the buffer
    }

    // ---- epilogue ----
    const float inv0 = 1.0f / l0v, inv1 = 1.0f / l1v;
    const int grow = q0 + row0;
#pragma unroll
    for (int dt = 0; dt < 16; dt++) {
        const int col = h * HD + dt * 8 + t4 * 2;
        float2 v0 = { oacc[dt][0] * inv0, oacc[dt][1] * inv0 };
        float2 v1 = { oacc[dt][2] * inv1, oacc[dt][3] * inv1 };
        *(float2*)&O[(size_t)grow * DIM + col]       = v0;
        *(float2*)&O[(size_t)(grow + 8) * DIM + col] = v1;
    }
}

// ---------------- launch -----------------------------------------------------
extern "C" void kernel_launch(void* const* d_in, const int* in_sizes, int n_in,
                              void* d_out, int out_size)
{
    const float* x  = (const float*)d_in[0];
    const float* wq = (const float*)d_in[1];
    const float* wk = (const float*)d_in[2];
    const float* wv = (const float*)d_in[3];
    const float* wo = (const float*)d_in[4];
    float* out = (float*)d_out;

    float *Qp, *Kp, *Vp, *Ap, *cp, *sp;
    cudaGetSymbolAddress((void**)&Qp, g_Q);
    cudaGetSymbolAddress((void**)&Kp, g_K);
    cudaGetSymbolAddress((void**)&Vp, g_V);
    cudaGetSymbolAddress((void**)&Ap, g_attn);
    cudaGetSymbolAddress((void**)&cp, g_cos);
    cudaGetSymbolAddress((void**)&sp, g_sin);

    __nv_bfloat16 *xh,*xl,*ah,*al,*wqh,*wql,*wkh,*wkl,*wvh,*wvl,*woh,*wol;
    __nv_bfloat16 *qsh,*qsl,*ksh,*ksl,*vth,*vtl;
    cudaGetSymbolAddress((void**)&xh,  g_xh);  cudaGetSymbolAddress((void**)&xl,  g_xl);
    cudaGetSymbolAddress((void**)&ah,  g_ah);  cudaGetSymbolAddress((void**)&al,  g_al);
    cudaGetSymbolAddress((void**)&wqh, g_wqh); cudaGetSymbolAddress((void**)&wql, g_wql);
    cudaGetSymbolAddress((void**)&wkh, g_wkh); cudaGetSymbolAddress((void**)&wkl, g_wkl);
    cudaGetSymbolAddress((void**)&wvh, g_wvh); cudaGetSymbolAddress((void**)&wvl, g_wvl);
    cudaGetSymbolAddress((void**)&woh, g_woh); cudaGetSymbolAddress((void**)&wol, g_wol);
    cudaGetSymbolAddress((void**)&qsh, g_qsh); cudaGetSymbolAddress((void**)&qsl, g_qsl);
    cudaGetSymbolAddress((void**)&ksh, g_ksh); cudaGetSymbolAddress((void**)&ksl, g_ksl);
    cudaGetSymbolAddress((void**)&vth, g_vth); cudaGetSymbolAddress((void**)&vtl, g_vtl);

    cudaFuncSetAttribute(tgemm_bf16s, cudaFuncAttributeMaxDynamicSharedMemorySize, TG_SMEM);
    cudaFuncSetAttribute(attn_hmma,   cudaFuncAttributeMaxDynamicSharedMemorySize, AT_SMEM);

    rope_tab_kernel<<<(SEQ*(HD/2) + 255)/256, 256>>>(cp, sp);

    // split inputs/weights
    split_bf16_kernel<<<(SEQ*DIM + 255)/256, 256>>>(x,  xh,  xl,  SEQ*DIM);
    split_bf16_kernel<<<(DIM*DIM + 255)/256, 256>>>(wq, wqh, wql, DIM*DIM);
    split_bf16_kernel<<<(KVDIM*DIM + 255)/256, 256>>>(wk, wkh, wkl, KVDIM*DIM);
    split_bf16_kernel<<<(KVDIM*DIM + 255)/256, 256>>>(wv, wvh, wvl, KVDIM*DIM);
    split_bf16_kernel<<<(DIM*DIM + 255)/256, 256>>>(wo, woh, wol, DIM*DIM);

    // projections (HMMA)
    tgemm_bf16s<<<dim3(DIM/128,   SEQ/128), TG_THREADS, TG_SMEM>>>(xh, xl, wqh, wql, Qp, SEQ, DIM,   DIM);
    tgemm_bf16s<<<dim3(KVDIM/128, SEQ/128), TG_THREADS, TG_SMEM>>>(xh, xl, wkh, wkl, Kp, SEQ, KVDIM, DIM);
    tgemm_bf16s<<<dim3(KVDIM/128, SEQ/128), TG_THREADS, TG_SMEM>>>(xh, xl, wvh, wvl, Vp, SEQ, KVDIM, DIM);

    rope_apply_kernel<<<(SEQ*NH*(HD/2))/256,   256>>>(Qp, cp, sp, NH);
    rope_apply_kernel<<<(SEQ*NKVH*(HD/2))/256, 256>>>(Kp, cp, sp, NKVH);

    // split post-RoPE Q/K and split+transpose V
    split_bf16_kernel<<<(SEQ*DIM + 255)/256, 256>>>(Qp, qsh, qsl, SEQ*DIM);
    split_bf16_kernel<<<(SEQ*KVDIM + 255)/256, 256>>>(Kp, ksh, ksl, SEQ*KVDIM);
    vt_split_kernel<<<(KVDIM*SEQ)/256, 256>>>(Vp, vth, vtl);

    // flash attention on tensor cores
    attn_hmma<<<dim3(SEQ/128, NH), 256, AT_SMEM>>>(qsh, qsl, ksh, ksl, vth, vtl, Ap);

    // output projection (HMMA)
    split_bf16_kernel<<<(SEQ*DIM + 255)/256, 256>>>(Ap, ah, al, SEQ*DIM);
    tgemm_bf16s<<<dim3(DIM/128, SEQ/128), TG_THREADS, TG_SMEM>>>(ah, al, woh, wol, out, SEQ, DIM, DIM);
}

// round 16
// speedup vs baseline: 2.9737x; 1.0155x over previous
#include <cuda_runtime.h>
#include <cuda_bf16.h>
#include <math.h>

#define SEQ   2048
#define DIM   4096
#define NH    32
#define NKVH  8
#define HD    128
#define KVDIM (NKVH*HD)   /* 1024 */

typedef unsigned long long ull;
typedef unsigned int uint;

// ---------------- scratch (device globals: no allocation allowed) -----------
__device__ __align__(256) float g_V[SEQ*KVDIM];
__device__ __align__(256) float g_cos[SEQ*(HD/2)];
__device__ __align__(256) float g_sin[SEQ*(HD/2)];
// split-bf16 operands (projection GEMMs)
__device__ __align__(256) __nv_bfloat16 g_xh[SEQ*DIM],   g_xl[SEQ*DIM];
__device__ __align__(256) __nv_bfloat16 g_ah[SEQ*DIM],   g_al[SEQ*DIM];
__device__ __align__(256) __nv_bfloat16 g_wqh[DIM*DIM],  g_wql[DIM*DIM];
__device__ __align__(256) __nv_bfloat16 g_wkh[KVDIM*DIM],g_wkl[KVDIM*DIM];
__device__ __align__(256) __nv_bfloat16 g_wvh[KVDIM*DIM],g_wvl[KVDIM*DIM];
__device__ __align__(256) __nv_bfloat16 g_woh[DIM*DIM],  g_wol[DIM*DIM];
// split-bf16 operands (attention)
__device__ __align__(256) __nv_bfloat16 g_qsh[SEQ*DIM],   g_qsl[SEQ*DIM];
__device__ __align__(256) __nv_bfloat16 g_ksh[SEQ*KVDIM], g_ksl[SEQ*KVDIM];
__device__ __align__(256) __nv_bfloat16 g_vth[KVDIM*SEQ], g_vtl[KVDIM*SEQ];

// ---------------- cp.async helpers ------------------------------------------
__device__ __forceinline__ uint smem_u32(const void* p) {
    uint a;
    asm("{ .reg .u64 t; cvta.to.shared.u64 t, %1; cvt.u32.u64 %0, t; }" : "=r"(a) : "l"(p));
    return a;
}
__device__ __forceinline__ void cp16(uint sdst, const void* gsrc) {
    asm volatile("cp.async.cg.shared.global [%0], [%1], 16;" :: "r"(sdst), "l"(gsrc));
}
#define CP_COMMIT() asm volatile("cp.async.commit_group;" ::: "memory")
#define CP_WAIT1()  asm volatile("cp.async.wait_group 1;" ::: "memory")
#define CP_WAIT0()  asm volatile("cp.async.wait_group 0;" ::: "memory")

// ---------------- mma.sync m16n8k16 bf16 (HW-validated) ----------------------
__device__ __forceinline__ void mma16816(float* d, const uint* a, const uint* b) {
    asm volatile(
        "mma.sync.aligned.m16n8k16.row.col.f32.bf16.bf16.f32 "
        "{%0,%1,%2,%3}, {%4,%5,%6,%7}, {%8,%9}, {%0,%1,%2,%3};"
        : "+f"(d[0]), "+f"(d[1]), "+f"(d[2]), "+f"(d[3])
        : "r"(a[0]), "r"(a[1]), "r"(a[2]), "r"(a[3]), "r"(b[0]), "r"(b[1]));
}

__device__ __forceinline__ uint packbf(float lo, float hi) {
    uint r;
    asm("cvt.rn.bf16x2.f32 %0, %1, %2;" : "=r"(r) : "f"(hi), "f"(lo));
    return r;
}

// ---------------- split-bf16 conversion --------------------------------------
__global__ void split_bf16_kernel(const float* __restrict__ in,
                                  __nv_bfloat16* __restrict__ hi,
                                  __nv_bfloat16* __restrict__ lo, int n)
{
    int i = blockIdx.x * blockDim.x + threadIdx.x;
    if (i >= n) return;
    float v = in[i];
    __nv_bfloat16 h = __float2bfloat16(v);
    hi[i] = h;
    lo[i] = __float2bfloat16(v - __bfloat162float(h));
}

// split V and transpose to [channel][seq]
__global__ void vt_split_kernel(const float* __restrict__ V,
                                __nv_bfloat16* __restrict__ vth,
                                __nv_bfloat16* __restrict__ vtl)
{
    int idx = blockIdx.x * blockDim.x + threadIdx.x;
    int s = idx & (SEQ - 1);
    int c = idx >> 11;
    float v = V[(size_t)s * KVDIM + c];
    __nv_bfloat16 h = __float2bfloat16(v);
    vth[idx] = h;
    vtl[idx] = __float2bfloat16(v - __bfloat162float(h));
}

// ---------------- RoPE table -------------------------------------------------
__global__ void rope_tab_kernel(float* __restrict__ cosT, float* __restrict__ sinT)
{
    int idx = blockIdx.x * blockDim.x + threadIdx.x;
    if (idx >= SEQ * (HD/2)) return;
    int s = idx / (HD/2);
    int i = idx % (HD/2);
    double freq = pow(500000.0, -(double)(2*i) / (double)HD);
    float ff = (float)freq;
    float ang = (float)s * ff;
    cosT[idx] = (float)cos((double)ang);
    sinT[idx] = (float)sin((double)ang);
}

// ---------------- HMMA split-bf16 GEMM ---------------------------------------
// mode 0: C fp32.  mode 1: rope on (even,odd) col pairs, write bf16 hi/lo.
#define TG_THREADS  256
#define TG_PITCH    72
#define TG_TILE_B   (128*TG_PITCH*2)
#define TG_STAGE_B  (4*TG_TILE_B)
#define TG_SMEM     (2*TG_STAGE_B)

__device__ __forceinline__ void tg_load_stage(
    uint sbase, const __nv_bfloat16* __restrict__ Ah, const __nv_bfloat16* __restrict__ Al,
    const __nv_bfloat16* __restrict__ Bh, const __nv_bfloat16* __restrict__ Bl,
    int m0, int n0, int k0, int K, int tid)
{
    const __nv_bfloat16* srcs[4] = {Ah, Al, Bh, Bl};
#pragma unroll
    for (int t = 0; t < 4; t++) {
        const __nv_bfloat16* s = srcs[t];
        const int r0 = (t < 2) ? m0 : n0;
        const uint tb = sbase + t * TG_TILE_B;
#pragma unroll
        for (int it = 0; it < 4; it++) {
            int cid = it * TG_THREADS + tid;
            int row = cid >> 3;
            int c16 = cid & 7;
            cp16(tb + row * (TG_PITCH*2) + c16 * 16,
                 s + (size_t)(r0 + row) * K + k0 + c16 * 8);
        }
    }
}

#define LDW(p, row, col) (*(const uint*)((p) + (((row)*TG_PITCH + (col)) << 1)))

__global__ __launch_bounds__(TG_THREADS, 1) void tgemm_bf16s(
    const __nv_bfloat16* __restrict__ Ah, const __nv_bfloat16* __restrict__ Al,
    const __nv_bfloat16* __restrict__ Bh, const __nv_bfloat16* __restrict__ Bl,
    float* __restrict__ C,
    __nv_bfloat16* __restrict__ Ch, __nv_bfloat16* __restrict__ Cl,
    const float* __restrict__ cosT, const float* __restrict__ sinT,
    int M, int N, int K, int mode)
{
    extern __shared__ char smem[];
    const uint sb32 = smem_u32(smem);
    const int tid = threadIdx.x;
    const int lane = tid & 31, wid = tid >> 5;
    const int warp_m = wid & 1, warp_n = wid >> 1;
    const int mbase = warp_m * 64, nbase = warp_n * 32;
    const int g = lane >> 2, t4 = lane & 3;
    const int m0 = blockIdx.y * 128, n0 = blockIdx.x * 128;

    float acc[4][4][4];
#pragma unroll
    for (int i = 0; i < 4; i++)
#pragma unroll
        for (int j = 0; j < 4; j++)
#pragma unroll
            for (int k = 0; k < 4; k++) acc[i][j][k] = 0.0f;

    const int nch = K >> 6;
    tg_load_stage(sb32, Ah, Al, Bh, Bl, m0, n0, 0, K, tid);
    CP_COMMIT();

    for (int ch = 0; ch < nch; ch++) {
        if (ch + 1 < nch) {
            tg_load_stage(sb32 + ((ch + 1) & 1) * TG_STAGE_B,
                          Ah, Al, Bh, Bl, m0, n0, (ch + 1) << 6, K, tid);
            CP_COMMIT();
            CP_WAIT1();
        } else {
            CP_WAIT0();
        }
        __syncthreads();

        const char* st  = smem + (ch & 1) * TG_STAGE_B;
        const char* pAh = st;
        const char* pAl = st + TG_TILE_B;
        const char* pBh = st + 2 * TG_TILE_B;
        const char* pBl = st + 3 * TG_TILE_B;

#pragma unroll
        for (int ks = 0; ks < 4; ks++) {
            const int kc = ks * 16 + t4 * 2;
            uint ah[4][4], al[4][4], bh[4][2], bl[4][2];
#pragma unroll
            for (int mt = 0; mt < 4; mt++) {
                int r = mbase + mt * 16 + g;
                ah[mt][0] = LDW(pAh, r,     kc);
                ah[mt][1] = LDW(pAh, r + 8, kc);
                ah[mt][2] = LDW(pAh, r,     kc + 8);
                ah[mt][3] = LDW(pAh, r + 8, kc + 8);
                al[mt][0] = LDW(pAl, r,     kc);
                al[mt][1] = LDW(pAl, r + 8, kc);
                al[mt][2] = LDW(pAl, r,     kc + 8);
                al[mt][3] = LDW(pAl, r + 8, kc + 8);
            }
#pragma unroll
            for (int nt = 0; nt < 4; nt++) {
                int nr = nbase + nt * 8 + g;
                bh[nt][0] = LDW(pBh, nr, kc);
                bh[nt][1] = LDW(pBh, nr, kc + 8);
                bl[nt][0] = LDW(pBl, nr, kc);
                bl[nt][1] = LDW(pBl, nr, kc + 8);
            }
            // pass-major: 16 independent accs between reuses
#pragma unroll
            for (int mt = 0; mt < 4; mt++)
#pragma unroll
                for (int nt = 0; nt < 4; nt++)
                    mma16816(acc[mt][nt], ah[mt], bh[nt]);
#pragma unroll
            for (int mt = 0; mt < 4; mt++)
#pragma unroll
                for (int nt = 0; nt < 4; nt++)
                    mma16816(acc[mt][nt], ah[mt], bl[nt]);
#pragma unroll
            for (int mt = 0; mt < 4; mt++)
#pragma unroll
                for (int nt = 0; nt < 4; nt++)
                    mma16816(acc[mt][nt], al[mt], bh[nt]);
        }
        __syncthreads();
    }

    if (mode == 0) {
#pragma unroll
        for (int mt = 0; mt < 4; mt++)
#pragma unroll
            for (int nt = 0; nt < 4; nt++) {
                int r = m0 + mbase + mt * 16 + g;
                int c = n0 + nbase + nt * 8 + t4 * 2;
                float2 v0 = {acc[mt][nt][0], acc[mt][nt][1]};
                float2 v1 = {acc[mt][nt][2], acc[mt][nt][3]};
                *(float2*)&C[(size_t)r * N + c]       = v0;
                *(float2*)&C[(size_t)(r + 8) * N + c] = v1;
            }
    } else {
        // rope (fp32) + split-bf16 epilogue
#pragma unroll
        for (int mt = 0; mt < 4; mt++)
#pragma unroll
            for (int nt = 0; nt < 4; nt++) {
                int r = m0 + mbase + mt * 16 + g;
                int c = n0 + nbase + nt * 8 + t4 * 2;
                int i = (c & (HD - 1)) >> 1;
                float cs0 = cosT[r * (HD/2) + i],       sn0 = sinT[r * (HD/2) + i];
                float cs1 = cosT[(r + 8) * (HD/2) + i], sn1 = sinT[(r + 8) * (HD/2) + i];
                float e0 = acc[mt][nt][0] * cs0 - acc[mt][nt][1] * sn0;
                float o0 = acc[mt][nt][0] * sn0 + acc[mt][nt][1] * cs0;
                float e1 = acc[mt][nt][2] * cs1 - acc[mt][nt][3] * sn1;
                float o1 = acc[mt][nt][2] * sn1 + acc[mt][nt][3] * cs1;
                uint h0 = packbf(e0, o0);
                uint l0 = packbf(e0 - __uint_as_float(h0 << 16),
                                 o0 - __uint_as_float(h0 & 0xFFFF0000u));
                uint h1 = packbf(e1, o1);
                uint l1 = packbf(e1 - __uint_as_float(h1 << 16),
                                 o1 - __uint_as_float(h1 & 0xFFFF0000u));
                *(uint*)&Ch[(size_t)r * N + c]       = h0;
                *(uint*)&Cl[(size_t)r * N + c]       = l0;
                *(uint*)&Ch[(size_t)(r + 8) * N + c] = h1;
                *(uint*)&Cl[(size_t)(r + 8) * N + c] = l1;
            }
    }
}

// ---------------- HMMA flash attention (split-bf16, causal, GQA) ------------
#define AT_SMEM  212992
#define QP 272
#define VP 144

__device__ __forceinline__ void at_load_kv(
    uint stage, const __nv_bfloat16* __restrict__ Kh, const __nv_bfloat16* __restrict__ Kl,
    const __nv_bfloat16* __restrict__ VTh, const __nv_bfloat16* __restrict__ VTl,
    int k0, int kvh, int tid)
{
#pragma unroll
    for (int it = 0; it < 8; it++) {
        int cid = it * 256 + tid;
        int tile = cid >> 10, c2 = cid & 1023;
        int r = c2 >> 4, c = c2 & 15;
        const __nv_bfloat16* src = (tile ? Kl : Kh) + (size_t)(k0 + r) * KVDIM + kvh * HD + c * 8;
        cp16(stage + tile * 17408 + r * QP + c * 16, src);
    }
#pragma unroll
    for (int it = 0; it < 8; it++) {
        int cid = it * 256 + tid;
        int tile = cid >> 10, c2 = cid & 1023;
        int r = c2 >> 3, c = c2 & 7;
        const __nv_bfloat16* src = (tile ? VTl : VTh) + (size_t)(kvh * HD + r) * SEQ + k0 + c * 8;
        cp16(stage + 34816 + tile * 18432 + r * VP + c * 16, src);
    }
}

__global__ __launch_bounds__(256, 1) void attn_hmma(
    const __nv_bfloat16* __restrict__ Qh, const __nv_bfloat16* __restrict__ Ql,
    const __nv_bfloat16* __restrict__ Kh, const __nv_bfloat16* __restrict__ Kl,
    const __nv_bfloat16* __restrict__ VTh, const __nv_bfloat16* __restrict__ VTl,
    __nv_bfloat16* __restrict__ Oh, __nv_bfloat16* __restrict__ Ol)
{
    extern __shared__ char sm_[];
    const uint sb = smem_u32(sm_);
    const int tid = threadIdx.x, lane = tid & 31, wid = tid >> 5;
    const int g = lane >> 2, t4 = lane & 3;
    const int qb = (int)gridDim.x - 1 - (int)blockIdx.x;
    const int q0 = qb * 128;
    const int h = blockIdx.y, kvh = h >> 2;
    const int nkb = 2 * qb + 2;
    const float scale = 0.08838834764831845f;
    const int row0 = wid * 16 + g;

#pragma unroll
    for (int it = 0; it < 16; it++) {
        int cid = it * 256 + tid;
        int tile = cid >> 11, c2 = cid & 2047;
        int r = c2 >> 4, c = c2 & 15;
        const __nv_bfloat16* src = (tile ? Ql : Qh) + (size_t)(q0 + r) * DIM + h * HD + c * 8;
        cp16(sb + tile * 34816 + r * QP + c * 16, src);
    }
    at_load_kv(sb + 69632, Kh, Kl, VTh, VTl, 0, kvh, tid);
    CP_COMMIT();

    float m0v = -INFINITY, m1v = -INFINITY, l0v = 0.0f, l1v = 0.0f;
    float oacc[16][4];
#pragma unroll
    for (int i = 0; i < 16; i++)
#pragma unroll
        for (int j = 0; j < 4; j++) oacc[i][j] = 0.0f;

    for (int kb = 0; kb < nkb; kb++) {
        if (kb + 1 < nkb) {
            at_load_kv(sb + 69632 + ((kb + 1) & 1) * 71680, Kh, Kl, VTh, VTl,
                       (kb + 1) * 64, kvh, tid);
            CP_COMMIT();
            CP_WAIT1();
        } else {
            CP_WAIT0();
        }
        __syncthreads();

        const char* pqh = sm_;
        const char* pql = sm_ + 34816;
        const char* pst = sm_ + 69632 + (size_t)(kb & 1) * 71680;
        const char* pkh = pst;
        const char* pkl = pst + 17408;
        const char* pvh = pst + 34816;
        const char* pvl = pst + 53248;

        // ---- S = Q K^T, pass-major in groups of 4 ----
        float sacc[8][4];
#pragma unroll
        for (int i = 0; i < 8; i++)
#pragma unroll
            for (int j = 0; j < 4; j++) sacc[i][j] = 0.0f;

#pragma unroll
        for (int ks = 0; ks < 8; ks++) {
            const int qw = ks * 8 + t4;
            uint qa_h[4], qa_l[4];
            qa_h[0] = *(const uint*)(pqh + (row0    ) * QP + qw * 4);
            qa_h[1] = *(const uint*)(pqh + (row0 + 8) * QP + qw * 4);
            qa_h[2] = *(const uint*)(pqh + (row0    ) * QP + (qw + 4) * 4);
            qa_h[3] = *(const uint*)(pqh + (row0 + 8) * QP + (qw + 4) * 4);
            qa_l[0] = *(const uint*)(pql + (row0    ) * QP + qw * 4);
            qa_l[1] = *(const uint*)(pql + (row0 + 8) * QP + qw * 4);
            qa_l[2] = *(const uint*)(pql + (row0    ) * QP + (qw + 4) * 4);
            qa_l[3] = *(const uint*)(pql + (row0 + 8) * QP + (qw + 4) * 4);
#pragma unroll
            for (int ng = 0; ng < 2; ng++) {
                uint kh4[4][2], kl4[4][2];
#pragma unroll
                for (int u = 0; u < 4; u++) {
                    const int kr = (ng * 4 + u) * 8 + g;
                    kh4[u][0] = *(const uint*)(pkh + kr * QP + qw * 4);
                    kh4[u][1] = *(const uint*)(pkh + kr * QP + (qw + 4) * 4);
                    kl4[u][0] = *(const uint*)(pkl + kr * QP + qw * 4);
                    kl4[u][1] = *(const uint*)(pkl + kr * QP + (qw + 4) * 4);
                }
#pragma unroll
                for (int u = 0; u < 4; u++) mma16816(sacc[ng*4+u], qa_h, kh4[u]);
#pragma unroll
                for (int u = 0; u < 4; u++) mma16816(sacc[ng*4+u], qa_h, kl4[u]);
#pragma unroll
                for (int u = 0; u < 4; u++) mma16816(sacc[ng*4+u], qa_l, kh4[u]);
            }
        }

        // ---- scale + causal mask + online softmax ----
        const int k0 = kb * 64;
        const bool diag = (kb >= nkb - 2);
#pragma unroll
        for (int nt = 0; nt < 8; nt++)
#pragma unroll
            for (int c = 0; c < 4; c++) {
                float v = sacc[nt][c] * scale;
                if (diag) {
                    int col  = k0 + nt * 8 + t4 * 2 + (c & 1);
                    int grow = q0 + row0 + ((c >> 1) << 3);
                    if (col > grow) v = -INFINITY;
                }
                sacc[nt][c] = v;
            }

        float vm0 = -INFINITY, vm1 = -INFINITY;
#pragma unroll
        for (int nt = 0; nt < 8; nt++) {
            vm0 = fmaxf(vm0, fmaxf(sacc[nt][0], sacc[nt][1]));
            vm1 = fmaxf(vm1, fmaxf(sacc[nt][2], sacc[nt][3]));
        }
        vm0 = fmaxf(vm0, __shfl_xor_sync(0xffffffffu, vm0, 1));
        vm0 = fmaxf(vm0, __shfl_xor_sync(0xffffffffu, vm0, 2));
        vm1 = fmaxf(vm1, __shfl_xor_sync(0xffffffffu, vm1, 1));
        vm1 = fmaxf(vm1, __shfl_xor_sync(0xffffffffu, vm1, 2));

        const float mn0 = fmaxf(m0v, vm0);
        const float mn1 = fmaxf(m1v, vm1);
        float ls0 = 0.0f, ls1 = 0.0f;
#pragma unroll
        for (int nt = 0; nt < 8; nt++) {
            float p0 = expf(sacc[nt][0] - mn0);
            float p1 = expf(sacc[nt][1] - mn0);
            float p2 = expf(sacc[nt][2] - mn1);
            float p3 = expf(sacc[nt][3] - mn1);
            sacc[nt][0] = p0; sacc[nt][1] = p1; sacc[nt][2] = p2; sacc[nt][3] = p3;
            ls0 += p0 + p1; ls1 += p2 + p3;
        }
        ls0 += __shfl_xor_sync(0xffffffffu, ls0, 1);
        ls0 += __shfl_xor_sync(0xffffffffu, ls0, 2);
        ls1 += __shfl_xor_sync(0xffffffffu, ls1, 1);
        ls1 += __shfl_xor_sync(0xffffffffu, ls1, 2);

        const float a0 = expf(m0v - mn0);
        const float a1 = expf(m1v - mn1);
        l0v = l0v * a0 + ls0;
        l1v = l1v * a1 + ls1;
        m0v = mn0; m1v = mn1;
#pragma unroll
        for (int dt = 0; dt < 16; dt++) {
            oacc[dt][0] *= a0; oacc[dt][1] *= a0;
            oacc[dt][2] *= a1; oacc[dt][3] *= a1;
        }

        // ---- O += P V, pass-major in groups of 4 ----
#pragma unroll
        for (int j = 0; j < 4; j++) {
            const float* sA = sacc[2 * j];
            const float* sB = sacc[2 * j + 1];
            uint pa_h[4], pa_l[4];
            pa_h[0] = packbf(sA[0], sA[1]);
            pa_h[1] = packbf(sA[2], sA[3]);
            pa_h[2] = packbf(sB[0], sB[1]);
            pa_h[3] = packbf(sB[2], sB[3]);
            pa_l[0] = packbf(sA[0] - __uint_as_float(pa_h[0] << 16),
                             sA[1] - __uint_as_float(pa_h[0] & 0xFFFF0000u));
            pa_l[1] = packbf(sA[2] - __uint_as_float(pa_h[1] << 16),
                             sA[3] - __uint_as_float(pa_h[1] & 0xFFFF0000u));
            pa_l[2] = packbf(sB[0] - __uint_as_float(pa_h[2] << 16),
                             sB[1] - __uint_as_float(pa_h[2] & 0xFFFF0000u));
            pa_l[3] = packbf(sB[2] - __uint_as_float(pa_h[3] << 16),
                             sB[3] - __uint_as_float(pa_h[3] & 0xFFFF0000u));
            const int vw = j * 8 + t4;
#pragma unroll
            for (int dg = 0; dg < 4; dg++) {
                uint vh4[4][2], vl4[4][2];
#pragma unroll
                for (int u = 0; u < 4; u++) {
                    const int vr = (dg * 4 + u) * 8 + g;
                    vh4[u][0] = *(const uint*)(pvh + vr * VP + vw * 4);
                    vh4[u][1] = *(const uint*)(pvh + vr * VP + (vw + 4) * 4);
                    vl4[u][0] = *(const uint*)(pvl + vr * VP + vw * 4);
                    vl4[u][1] = *(const uint*)(pvl + vr * VP + (vw + 4) * 4);
                }
#pragma unroll
                for (int u = 0; u < 4; u++) mma16816(oacc[dg*4+u], pa_h, vh4[u]);
#pragma unroll
                for (int u = 0; u < 4; u++) mma16816(oacc[dg*4+u], pa_h, vl4[u]);
#pragma unroll
                for (int u = 0; u < 4; u++) mma16816(oacc[dg*4+u], pa_l, vh4[u]);
            }
        }
        __syncthreads();
    }

    // ---- epilogue: split-bf16 out (feeds O-projection) ----
    const float inv0 = 1.0f / l0v, inv1 = 1.0f / l1v;
    const int grow = q0 + row0;
#pragma unroll
    for (int dt = 0; dt < 16; dt++) {
        const int col = h * HD + dt * 8 + t4 * 2;
        float e0 = oacc[dt][0] * inv0, o0 = oacc[dt][1] * inv0;
        float e1 = oacc[dt][2] * inv1, o1 = oacc[dt][3] * inv1;
        uint h0 = packbf(e0, o0);
        uint l0 = packbf(e0 - __uint_as_float(h0 << 16),
                         o0 - __uint_as_float(h0 & 0xFFFF0000u));
        uint h1 = packbf(e1, o1);
        uint l1 = packbf(e1 - __uint_as_float(h1 << 16),
                         o1 - __uint_as_float(h1 & 0xFFFF0000u));
        *(uint*)&Oh[(size_t)grow * DIM + col]       = h0;
        *(uint*)&Ol[(size_t)grow * DIM + col]       = l0;
        *(uint*)&Oh[(size_t)(grow + 8) * DIM + col] = h1;
        *(uint*)&Ol[(size_t)(grow + 8) * DIM + col] = l1;
    }
}

// ---------------- launch -----------------------------------------------------
extern "C" void kernel_launch(void* const* d_in, const int* in_sizes, int n_in,
                              void* d_out, int out_size)
{
    const float* x  = (const float*)d_in[0];
    const float* wq = (const float*)d_in[1];
    const float* wk = (const float*)d_in[2];
    const float* wv = (const float*)d_in[3];
    const float* wo = (const float*)d_in[4];
    float* out = (float*)d_out;

    float *Vp, *cp, *sp;
    cudaGetSymbolAddress((void**)&Vp, g_V);
    cudaGetSymbolAddress((void**)&cp, g_cos);
    cudaGetSymbolAddress((void**)&sp, g_sin);

    __nv_bfloat16 *xh,*xl,*ah,*al,*wqh,*wql,*wkh,*wkl,*wvh,*wvl,*woh,*wol;
    __nv_bfloat16 *qsh,*qsl,*ksh,*ksl,*vth,*vtl;
    cudaGetSymbolAddress((void**)&xh,  g_xh);  cudaGetSymbolAddress((void**)&xl,  g_xl);
    cudaGetSymbolAddress((void**)&ah,  g_ah);  cudaGetSymbolAddress((void**)&al,  g_al);
    cudaGetSymbolAddress((void**)&wqh, g_wqh); cudaGetSymbolAddress((void**)&wql, g_wql);
    cudaGetSymbolAddress((void**)&wkh, g_wkh); cudaGetSymbolAddress((void**)&wkl, g_wkl);
    cudaGetSymbolAddress((void**)&wvh, g_wvh); cudaGetSymbolAddress((void**)&wvl, g_wvl);
    cudaGetSymbolAddress((void**)&woh, g_woh); cudaGetSymbolAddress((void**)&wol, g_wol);
    cudaGetSymbolAddress((void**)&qsh, g_qsh); cudaGetSymbolAddress((void**)&qsl, g_qsl);
    cudaGetSymbolAddress((void**)&ksh, g_ksh); cudaGetSymbolAddress((void**)&ksl, g_ksl);
    cudaGetSymbolAddress((void**)&vth, g_vth); cudaGetSymbolAddress((void**)&vtl, g_vtl);

    cudaFuncSetAttribute(tgemm_bf16s, cudaFuncAttributeMaxDynamicSharedMemorySize, TG_SMEM);
    cudaFuncSetAttribute(attn_hmma,   cudaFuncAttributeMaxDynamicSharedMemorySize, AT_SMEM);

    rope_tab_kernel<<<(SEQ*(HD/2) + 255)/256, 256>>>(cp, sp);

    // split inputs/weights
    split_bf16_kernel<<<(SEQ*DIM + 255)/256, 256>>>(x,  xh,  xl,  SEQ*DIM);
    split_bf16_kernel<<<(DIM*DIM + 255)/256, 256>>>(wq, wqh, wql, DIM*DIM);
    split_bf16_kernel<<<(KVDIM*DIM + 255)/256, 256>>>(wk, wkh, wkl, KVDIM*DIM);
    split_bf16_kernel<<<(KVDIM*DIM + 255)/256, 256>>>(wv, wvh, wvl, KVDIM*DIM);
    split_bf16_kernel<<<(DIM*DIM + 255)/256, 256>>>(wo, woh, wol, DIM*DIM);

    // Q/K projections with fused rope + split-bf16 epilogue
    tgemm_bf16s<<<dim3(DIM/128,   SEQ/128), TG_THREADS, TG_SMEM>>>(
        xh, xl, wqh, wql, nullptr, qsh, qsl, cp, sp, SEQ, DIM,   DIM, 1);
    tgemm_bf16s<<<dim3(KVDIM/128, SEQ/128), TG_THREADS, TG_SMEM>>>(
        xh, xl, wkh, wkl, nullptr, ksh, ksl, cp, sp, SEQ, KVDIM, DIM, 1);
    // V projection (fp32 out), then split+transpose
    tgemm_bf16s<<<dim3(KVDIM/128, SEQ/128), TG_THREADS, TG_SMEM>>>(
        xh, xl, wvh, wvl, Vp, nullptr, nullptr, nullptr, nullptr, SEQ, KVDIM, DIM, 0);
    vt_split_kernel<<<(KVDIM*SEQ)/256, 256>>>(Vp, vth, vtl);

    // flash attention on tensor cores -> bf16 hi/lo
    attn_hmma<<<dim3(SEQ/128, NH), 256, AT_SMEM>>>(qsh, qsl, ksh, ksl, vth, vtl, ah, al);

    // output projection (fp32 out)
    tgemm_bf16s<<<dim3(DIM/128, SEQ/128), TG_THREADS, TG_SMEM>>>(
        ah, al, woh, wol, out, nullptr, nullptr, nullptr, nullptr, SEQ, DIM, DIM, 0);
}